// round 11
// baseline (speedup 1.0000x reference)
#include <cuda_runtime.h>
#include <cuda_bf16.h>

// DynamicUpsamplingFilter: out[b,c,h,w] = sum_{dy,dx} x[b,c,h+dy-1,w+dx-1] * filters[b,dy*3+dx,h,w]
// x [4,128,180,320] f32, filters [4,9,180,320] f32, out [4,128,180,320] f32.
//
// R11: 2 pixels/thread + double-buffered channel pipeline + 3 CTAs/SM.
// Register demand engineered BELOW the cap (filters 18 regs, buffers 2x15,
// total ~66 <= 84 @ launch_bounds(256,3)) so ptxas keeps the full load-ahead
// schedule (R9/R10 were pinned at 128 and partially serialized). Halos via
// R5's contiguous loads (float2 at w-2 -> .y is x(w-1); scalar at w+2):
// no shuffles, no selects, compute phase is pure FMA. Boundary handling
// hoisted into zeroed coefficients + clamped offsets; hot loop branch-free.

#define B_ 4
#define C_ 128
#define H_ 180
#define W_ 320
#define CPB 32           // channels per block (grid.y = 4)
#define TPB 256

__global__ __launch_bounds__(TPB, 3)
void duf_kernel(const float* __restrict__ x,
                const float* __restrict__ filters,
                float* __restrict__ out)
{
    const int HW = H_ * W_;
    int tid = blockIdx.x * TPB + threadIdx.x;
    const int WH = W_ / 2;             // 160 pixel-pairs per row
    int wh = tid % WH;
    int t2 = tid / WH;
    int h  = t2 % H_;
    int b  = t2 / H_;
    int w  = wh * 2;

    int c0 = blockIdx.y * CPB;

    // ---- 9 filter float2s (tap i, pixels w, w+1) ----
    const float* fb = filters + ((size_t)b * 9) * HW + (size_t)h * W_ + w;
    float2 f[9];
#pragma unroll
    for (int i = 0; i < 9; i++)
        f[i] = __ldg((const float2*)(fb + (size_t)i * HW));

    // ---- boundary masks folded into coefficients ----
    if (h == 0) {
        f[0] = make_float2(0.f, 0.f);
        f[1] = make_float2(0.f, 0.f);
        f[2] = make_float2(0.f, 0.f);
    }
    if (h == H_ - 1) {
        f[6] = make_float2(0.f, 0.f);
        f[7] = make_float2(0.f, 0.f);
        f[8] = make_float2(0.f, 0.f);
    }
    if (w == 0) {                  // pixel0 left taps off the edge
        f[0].x = 0.f; f[3].x = 0.f; f[6].x = 0.f;
    }
    if (w + 2 == W_) {             // pixel1 right taps off the edge
        f[2].y = 0.f; f[5].y = 0.f; f[8].y = 0.f;
    }

    // clamped offsets (clamped values hit zeroed coefficients)
    int hm  = (h > 0)      ? h - 1 : 0;
    int hp  = (h < H_ - 1) ? h + 1 : h;
    int wl2 = (w >= 2)     ? w - 2 : 0;        // float2 covering [w-2, w-1]
    int ws  = (w + 2 < W_) ? w + 2 : W_ - 1;   // scalar x(w+2)

    const float* base = x + ((size_t)(b * C_ + c0)) * HW;
    const float* pm = base + (size_t)hm * W_;   // load-side pointers
    const float* p0 = base + (size_t)h  * W_;
    const float* pp = base + (size_t)hp * W_;
    float* po = out + (((size_t)(b * C_ + c0)) * H_ + h) * (size_t)W_ + w;

    // double-buffered registers: one channel per buffer (15 regs each)
    float2 Avm, Alm, Av0, Al0, Avp, Alp;
    float  Asm, As0, Asp;
    float2 Bvm, Blm, Bv0, Bl0, Bvp, Blp;
    float  Bsm, Bs0, Bsp;

#define LOADB(P)                                                        \
    {                                                                   \
        P##vm = __ldg((const float2*)(pm + w));                         \
        P##lm = __ldg((const float2*)(pm + wl2));                       \
        P##sm = __ldg(pm + ws);                                         \
        P##v0 = __ldg((const float2*)(p0 + w));                         \
        P##l0 = __ldg((const float2*)(p0 + wl2));                       \
        P##s0 = __ldg(p0 + ws);                                         \
        P##vp = __ldg((const float2*)(pp + w));                         \
        P##lp = __ldg((const float2*)(pp + wl2));                       \
        P##sp = __ldg(pp + ws);                                         \
        pm += HW; p0 += HW; pp += HW;                                   \
    }

#define COMPUTEB(P)                                                     \
    {                                                                   \
        float2 acc;                                                     \
        acc.x = f[0].x*P##lm.y + f[1].x*P##vm.x + f[2].x*P##vm.y        \
              + f[3].x*P##l0.y + f[4].x*P##v0.x + f[5].x*P##v0.y        \
              + f[6].x*P##lp.y + f[7].x*P##vp.x + f[8].x*P##vp.y;       \
        acc.y = f[0].y*P##vm.x + f[1].y*P##vm.y + f[2].y*P##sm          \
              + f[3].y*P##v0.x + f[4].y*P##v0.y + f[5].y*P##s0          \
              + f[6].y*P##vp.x + f[7].y*P##vp.y + f[8].y*P##sp;         \
        *((float2*)po) = acc;                                           \
        po += HW;                                                       \
    }

    // ---- 2-deep pipeline over CPB channels ----
    LOADB(A);
#pragma unroll 1
    for (int c = 0; c < CPB - 2; c += 2) {
        LOADB(B);              // next channel in flight while computing current
        COMPUTEB(A);
        LOADB(A);
        COMPUTEB(B);
    }
    LOADB(B);
    COMPUTEB(A);
    COMPUTEB(B);

#undef LOADB
#undef COMPUTEB
}

extern "C" void kernel_launch(void* const* d_in, const int* in_sizes, int n_in,
                              void* d_out, int out_size)
{
    const float* x       = (const float*)d_in[0];
    const float* filters = (const float*)d_in[1];
    float* out           = (float*)d_out;

    int spatial_threads = B_ * H_ * (W_ / 2);     // 115200
    dim3 grid(spatial_threads / TPB, C_ / CPB);   // (450, 4) = 1800 blocks
    duf_kernel<<<grid, TPB>>>(x, filters, out);
}

// round 12
// speedup vs baseline: 1.2358x; 1.2358x over previous
#include <cuda_runtime.h>
#include <cuda_bf16.h>

// DynamicUpsamplingFilter: out[b,c,h,w] = sum_{dy,dx} x[b,c,h+dy-1,w+dx-1] * filters[b,dy*3+dx,h,w]
// x [4,128,180,320] f32, filters [4,9,180,320] f32, out [4,128,180,320] f32.
//
// R12: R10's pipelined 4px kernel, but launched as 128-thread blocks with
// __launch_bounds__(128,3) -> per-thread register cap 170 instead of 128.
// R9/R10 were pinned at exactly 128 regs (2CTA x 256thr budget) which forced
// ptxas to serialize part of the double-buffer look-ahead. With ~40 regs of
// slack the full pipeline schedule (load batch i+1 entirely above compute of
// batch i) stays intact. Packed edge values (one scalar serves lane0-left /
// lane31-right), shuffle halos, boundary masks hoisted into coefficients.

#define B_ 4
#define C_ 128
#define H_ 180
#define W_ 320
#define CPB 32           // channels per block (grid.y = 4)
#define TPB 128
#define U   2            // channels per pipeline batch; 16 batches

__global__ __launch_bounds__(TPB, 3)
void duf_kernel(const float* __restrict__ x,
                const float* __restrict__ filters,
                float* __restrict__ out)
{
    const int HW = H_ * W_;
    int tid = blockIdx.x * TPB + threadIdx.x;
    const int WQ = W_ / 4;             // 80 pixel-quads per row
    int wq = tid % WQ;
    int t2 = tid / WQ;
    int h  = t2 % H_;
    int b  = t2 / H_;
    int w  = wq * 4;
    int lane = threadIdx.x & 31;

    int c0 = blockIdx.y * CPB;

    // ---- 9 filter float4s (tap i, pixels w..w+3) ----
    const float* fb = filters + ((size_t)b * 9) * HW + (size_t)h * W_ + w;
    float4 f[9];
#pragma unroll
    for (int i = 0; i < 9; i++)
        f[i] = __ldg((const float4*)(fb + (size_t)i * HW));

    // ---- boundary masks folded into coefficients ----
    if (h == 0) {
        f[0] = make_float4(0,0,0,0);
        f[1] = make_float4(0,0,0,0);
        f[2] = make_float4(0,0,0,0);
    }
    if (h == H_ - 1) {
        f[6] = make_float4(0,0,0,0);
        f[7] = make_float4(0,0,0,0);
        f[8] = make_float4(0,0,0,0);
    }
    if (w == 0) {                  // pixel0 left taps (also kills row-cross shfl garbage)
        f[0].x = 0.f; f[3].x = 0.f; f[6].x = 0.f;
    }
    if (w + 4 == W_) {             // pixel3 right taps (ditto)
        f[2].w = 0.f; f[5].w = 0.f; f[8].w = 0.f;
    }

    // clamped offsets (clamped values hit zeroed coefficients)
    int hm = (h > 0)      ? h - 1 : 0;
    int hp = (h < H_ - 1) ? h + 1 : h;
    int wl = (w > 0)      ? w - 1 : 0;        // scalar x(w-1)
    int wr = (w + 4 < W_) ? w + 4 : W_ - 1;   // scalar x(w+4)

    const bool ld_l = (lane == 0);
    const bool ld_r = (lane == 31);
    const bool ld_e = ld_l | ld_r;            // this lane loads ONE edge value
    const int  eoff = ld_l ? wl : wr;

    const float* base = x + ((size_t)(b * C_ + c0)) * HW;
    const float* pm = base + (size_t)hm * W_;   // load-side pointers
    const float* p0 = base + (size_t)h  * W_;
    const float* pp = base + (size_t)hp * W_;
    float* po = out + (((size_t)(b * C_ + c0)) * H_ + h) * (size_t)W_ + w;

    // double-buffered registers: 6 float4 + 6 packed-edge scalars per buffer
    float4 Avm[U], Av0[U], Avp[U], Bvm[U], Bv0[U], Bvp[U];
    float  Aem[U], Ae0[U], Aep[U], Bem[U], Be0[U], Bep[U];

#define LOADB(P)                                                        \
    {                                                                   \
        _Pragma("unroll")                                               \
        for (int u = 0; u < U; u++) {                                   \
            const float* qm = pm + (size_t)u * HW;                      \
            const float* q0 = p0 + (size_t)u * HW;                      \
            const float* qp = pp + (size_t)u * HW;                      \
            P##vm[u] = __ldg((const float4*)(qm + w));                  \
            P##v0[u] = __ldg((const float4*)(q0 + w));                  \
            P##vp[u] = __ldg((const float4*)(qp + w));                  \
            P##em[u] = ld_e ? __ldg(qm + eoff) : 0.f;                   \
            P##e0[u] = ld_e ? __ldg(q0 + eoff) : 0.f;                   \
            P##ep[u] = ld_e ? __ldg(qp + eoff) : 0.f;                   \
        }                                                               \
        pm += (size_t)U * HW; p0 += (size_t)U * HW; pp += (size_t)U * HW; \
    }

#define COMPUTEB(P)                                                     \
    {                                                                   \
        _Pragma("unroll")                                               \
        for (int u = 0; u < U; u++) {                                   \
            float sml = __shfl_up_sync(0xffffffffu,  P##vm[u].w, 1);    \
            float s0l = __shfl_up_sync(0xffffffffu,  P##v0[u].w, 1);    \
            float spl = __shfl_up_sync(0xffffffffu,  P##vp[u].w, 1);    \
            float smr = __shfl_down_sync(0xffffffffu, P##vm[u].x, 1);   \
            float s0r = __shfl_down_sync(0xffffffffu, P##v0[u].x, 1);   \
            float spr = __shfl_down_sync(0xffffffffu, P##vp[u].x, 1);   \
            float vml = ld_l ? P##em[u] : sml;                          \
            float v0l = ld_l ? P##e0[u] : s0l;                          \
            float vpl = ld_l ? P##ep[u] : spl;                          \
            float vmr = ld_r ? P##em[u] : smr;                          \
            float v0r = ld_r ? P##e0[u] : s0r;                          \
            float vpr = ld_r ? P##ep[u] : spr;                          \
            float4 acc;                                                 \
            acc.x = f[0].x*vml        + f[1].x*P##vm[u].x + f[2].x*P##vm[u].y \
                  + f[3].x*v0l        + f[4].x*P##v0[u].x + f[5].x*P##v0[u].y \
                  + f[6].x*vpl        + f[7].x*P##vp[u].x + f[8].x*P##vp[u].y; \
            acc.y = f[0].y*P##vm[u].x + f[1].y*P##vm[u].y + f[2].y*P##vm[u].z \
                  + f[3].y*P##v0[u].x + f[4].y*P##v0[u].y + f[5].y*P##v0[u].z \
                  + f[6].y*P##vp[u].x + f[7].y*P##vp[u].y + f[8].y*P##vp[u].z; \
            acc.z = f[0].z*P##vm[u].y + f[1].z*P##vm[u].z + f[2].z*P##vm[u].w \
                  + f[3].z*P##v0[u].y + f[4].z*P##v0[u].z + f[5].z*P##v0[u].w \
                  + f[6].z*P##vp[u].y + f[7].z*P##vp[u].z + f[8].z*P##vp[u].w; \
            acc.w = f[0].w*P##vm[u].z + f[1].w*P##vm[u].w + f[2].w*vmr   \
                  + f[3].w*P##v0[u].z + f[4].w*P##v0[u].w + f[5].w*v0r   \
                  + f[6].w*P##vp[u].z + f[7].w*P##vp[u].w + f[8].w*vpr;  \
            *((float4*)(po + (size_t)u * HW)) = acc;                    \
        }                                                               \
        po += (size_t)U * HW;                                           \
    }

    // ---- 2-deep pipeline over CPB/U = 16 batches ----
    LOADB(A);
#pragma unroll 1
    for (int cb = 0; cb < CPB / U - 2; cb += 2) {
        LOADB(B);                   // next batch in flight while computing current
        COMPUTEB(A);
        LOADB(A);
        COMPUTEB(B);
    }
    LOADB(B);
    COMPUTEB(A);
    COMPUTEB(B);

#undef LOADB
#undef COMPUTEB
}

extern "C" void kernel_launch(void* const* d_in, const int* in_sizes, int n_in,
                              void* d_out, int out_size)
{
    const float* x       = (const float*)d_in[0];
    const float* filters = (const float*)d_in[1];
    float* out           = (float*)d_out;

    int spatial_threads = B_ * H_ * (W_ / 4);     // 57600
    dim3 grid(spatial_threads / TPB, C_ / CPB);   // (450, 4) = 1800 blocks
    duf_kernel<<<grid, TPB>>>(x, filters, out);
}